// round 13
// baseline (speedup 1.0000x reference)
#include <cuda_runtime.h>

// Problem constants
#define B_   2
#define N_   4
#define BN_  8
#define C_   64
#define HF_  64
#define WF_  64
#define XV_  128
#define YV_  128
#define ZV_  8
#define HW_  (HF_ * WF_)          // 4096

#define ROWF4_  (C_ / 4)          // float4 per pixel: 16
#define LINEF4_ (WF_ * ROWF4_)    // float4 per image row: 1024

// Scratch (allocations forbidden -> __device__ globals)
__device__ float g_featsT[BN_ * HW_ * C_];  // feats transposed to (bn, h, w, c)

// ---------------------------------------------------------------------------
// Kernel 1: transpose feats (bn, c, hw) -> (bn, hw, c), float4 both sides.
// Fires the PDL trigger at the end so the main kernel's blocks can launch
// and run their projection preamble while the transpose tail drains.
// ---------------------------------------------------------------------------
__global__ void __launch_bounds__(256) transpose_feats_kernel(
        const float* __restrict__ feats) {
    __shared__ float tile[32][33];
    int bn = blockIdx.z;
    int c0 = blockIdx.y * 32;
    int p0 = blockIdx.x * 32;
    int tx = threadIdx.x & 7;    // p-float4 index within tile
    int ty = threadIdx.x >> 3;   // c row 0..31

    const float4* in4 = (const float4*)(feats + (size_t)bn * C_ * HW_);
    float4 v = in4[(((c0 + ty) * HW_ + p0) >> 2) + tx];
    tile[ty][4 * tx + 0] = v.x;
    tile[ty][4 * tx + 1] = v.y;
    tile[ty][4 * tx + 2] = v.z;
    tile[ty][4 * tx + 3] = v.w;
    __syncthreads();

    float4 w;
    w.x = tile[4 * tx + 0][ty];
    w.y = tile[4 * tx + 1][ty];
    w.z = tile[4 * tx + 2][ty];
    w.w = tile[4 * tx + 3][ty];
    float4* out4 = (float4*)(g_featsT + (size_t)bn * HW_ * C_);
    out4[(((p0 + ty) * C_ + c0) >> 2) + tx] = w;

#if __CUDA_ARCH__ >= 900
    cudaTriggerProgrammaticLaunchCompletion();
#endif
}

// ---------------------------------------------------------------------------
// Kernel 2: THE R5 CHAMPION main kernel (27.68us measured), unchanged hot
// loop, with two dependency-restructuring additions:
//   * per-block camera-matrix precompute (8 threads, identical FP ops to the
//     old block-0 precompute -> bit-identical projections), removing the
//     g_mats dependency on kernel 1
//   * cudaGridDependencySynchronize() placed AFTER projection + weights and
//     BEFORE the first gather: with PDL, the whole preamble overlaps the
//     transpose instead of serializing behind it
// ---------------------------------------------------------------------------
__global__ void __launch_bounds__(128, 9) bev_unproject_kernel(
        const float* __restrict__ intrins,
        const float* __restrict__ extrins,
        float* __restrict__ out) {
    int t = blockIdx.x * 128 + threadIdx.x;
    int y = t & 127;
    int x = (t >> 7) & 127;
    int z = (t >> 14) & 7;
    int b = t >> 17;

    // per-block matrix precompute (reads only kernel inputs, not g_featsT)
    __shared__ float sm[BN_ * 12];
    if (threadIdx.x < BN_) {
        int bn = threadIdx.x;
        const float* E = extrins + bn * 16;
        const float* K = intrins + bn * 16;
        float M[3][4];
#pragma unroll
        for (int i = 0; i < 3; i++) {
            float r0 = E[0 * 4 + i];
            float r1 = E[1 * 4 + i];
            float r2 = E[2 * 4 + i];
            M[i][0] = r0; M[i][1] = r1; M[i][2] = r2;
            M[i][3] = -(r0 * E[3] + r1 * E[7] + r2 * E[11]);
        }
        float fx = K[0] * 0.125f;
        float fy = K[5] * 0.125f;
        float x0 = K[2] * 0.125f;
        float y0 = K[6] * 0.125f;
        float* P = sm + bn * 12;
#pragma unroll
        for (int k = 0; k < 4; k++) {
            P[0 * 4 + k] = fx * M[0][k] + x0 * M[2][k];
            P[1 * 4 + k] = fy * M[1][k] + y0 * M[2][k];
            P[2 * 4 + k] = M[2][k];
        }
    }
    __syncthreads();

    // voxel center in cam0/ref coords
    float X = (float)x * 0.8f - 50.8f;
    float Y = (float)y * 0.8f - 50.8f;
    float Z = (float)z * 0.5f - 2.75f;

    const float4* __restrict__ F = (const float4*)g_featsT;
    const float4* p[4];          // per-camera corner00 base pointer
    float ax0[4], ax1[4], ay0[4], ay1[4];
    int mask = 0;

#pragma unroll
    for (int n = 0; n < 4; n++) {
        const float* P = sm + (b * 4 + n) * 12;
        float xp = P[0] * X + P[1] * Y + P[2]  * Z + P[3];
        float yp = P[4] * X + P[5] * Y + P[6]  * Z + P[7];
        float zc = P[8] * X + P[9] * Y + P[10] * Z + P[11];

        float r  = 1.0f / fmaxf(zc, 1e-6f);   // one exact div, two muls
        float sx = xp * r;
        float sy = yp * r;

        bool valid = (sx > -0.5f) & (sx < 63.5f) & (sy > -0.5f) & (sy < 63.5f) & (zc > 0.0f);

        p[n] = F;
        ax0[n] = ax1[n] = ay0[n] = ay1[n] = 0.0f;

        if (valid) {
            float px = sx - 0.5f, py = sy - 0.5f;
            float x0f = floorf(px), y0f = floorf(py);
            float wx = px - x0f,    wy = py - y0f;
            int xi = (int)x0f;      // in [-1, 62]; xi+1 always in-bounds
            int yi = (int)y0f;      // in [-1, 62]; yi+1 always in-bounds
            bool lv = (xi >= 0);
            bool tv = (yi >= 0);
            int xc = lv ? xi : 0;
            int yc = tv ? yi : 0;
            // per-axis weights with edge swap (bit-identical products)
            ax0[n] = lv ? (1.0f - wx) : wx;
            ax1[n] = lv ? wx : 0.0f;
            ay0[n] = tv ? (1.0f - wy) : wy;
            ay1[n] = tv ? wy : 0.0f;
            int bn = b * 4 + n;
            p[n] = F + (size_t)((bn * HF_ + yc) * WF_ + xc) * ROWF4_;
            mask |= (1 << n);
        }
    }

    // fold 1/(eps + #valid) into the y-axis weights
    int cnt = __popc(mask);
    const float r1 = 1.0f / (1e-6f + 1.0f);
    const float r2 = 1.0f / (1e-6f + 2.0f);
    const float r3 = 1.0f / (1e-6f + 3.0f);
    const float r4 = 1.0f / (1e-6f + 4.0f);
    float rcp = (cnt <= 1) ? r1 : (cnt == 2) ? r2 : (cnt == 3) ? r3 : r4;

    float w00[4], w10[4], w01[4], w11[4];
#pragma unroll
    for (int n = 0; n < 4; n++) {
        float sy0 = ay0[n] * rcp, sy1 = ay1[n] * rcp;
        w00[n] = ax0[n] * sy0;
        w10[n] = ax1[n] * sy0;
        w01[n] = ax0[n] * sy1;
        w11[n] = ax1[n] * sy1;
    }

    // wait here (not at launch) for the transpose's g_featsT to be visible
#if __CUDA_ARCH__ >= 900
    cudaGridDependencySynchronize();
#endif

    // out[b, c*8+z, x, y]
    float* ob = out + ((b * C_) * ZV_ + z) * (XV_ * YV_) + x * YV_ + y;
    const int cstride = ZV_ * XV_ * YV_;   // 131072

#pragma unroll
    for (int ch = 0; ch < C_ / 8; ch++) {   // 8 channels = 2 float4 per corner
        float acc[8] = {0.f, 0.f, 0.f, 0.f, 0.f, 0.f, 0.f, 0.f};
#pragma unroll
        for (int n = 0; n < 4; n++) {
            if (mask & (1 << n)) {
                const float4* q = p[n] + ch * 2;
                float a = w00[n], bw = w10[n], c2 = w01[n], d = w11[n];
#pragma unroll
                for (int k = 0; k < 2; k++) {
                    float4 g00 = __ldg(q + k);
                    float4 g10 = __ldg(q + k + ROWF4_);             // +16
                    float4 g01 = __ldg(q + k + LINEF4_);            // +1024
                    float4 g11 = __ldg(q + k + LINEF4_ + ROWF4_);   // +1040
                    acc[4 * k + 0] += ((g00.x * a + g10.x * bw) + g01.x * c2) + g11.x * d;
                    acc[4 * k + 1] += ((g00.y * a + g10.y * bw) + g01.y * c2) + g11.y * d;
                    acc[4 * k + 2] += ((g00.z * a + g10.z * bw) + g01.z * c2) + g11.z * d;
                    acc[4 * k + 3] += ((g00.w * a + g10.w * bw) + g01.w * c2) + g11.w * d;
                }
            }
        }
#pragma unroll
        for (int j = 0; j < 8; j++) {
            ob[(8 * ch + j) * cstride] = acc[j];
        }
    }
}

// ---------------------------------------------------------------------------
extern "C" void kernel_launch(void* const* d_in, const int* in_sizes, int n_in,
                              void* d_out, int out_size) {
    const float* feats   = (const float*)d_in[0];  // (2,4,64,64,64)
    const float* intrins = (const float*)d_in[1];  // (2,4,4,4)
    const float* extrins = (const float*)d_in[2];  // (2,4,4,4)
    float* out = (float*)d_out;                    // (2,512,128,128)

    dim3 tgrid(HW_ / 32, C_ / 32, BN_);
    transpose_feats_kernel<<<tgrid, 256>>>(feats);

    // main kernel with Programmatic Dependent Launch: its blocks may start
    // (and run the projection preamble) before the transpose finishes; the
    // in-kernel cudaGridDependencySynchronize() guards the gathers.
    cudaLaunchConfig_t cfg = {};
    cfg.gridDim  = dim3((B_ * ZV_ * XV_ * YV_) / 128);   // 2048
    cfg.blockDim = dim3(128);
    cfg.dynamicSmemBytes = 0;
    cfg.stream = 0;
    cudaLaunchAttribute attrs[1];
    attrs[0].id = cudaLaunchAttributeProgrammaticStreamSerialization;
    attrs[0].val.programmaticStreamSerializationAllowed = 1;
    cfg.attrs = attrs;
    cfg.numAttrs = 1;
    cudaLaunchKernelEx(&cfg, bev_unproject_kernel, intrins, extrins, out);
}

// round 14
// speedup vs baseline: 1.0113x; 1.0113x over previous
#include <cuda_runtime.h>

// Problem constants
#define B_   2
#define N_   4
#define BN_  8
#define C_   64
#define HF_  64
#define WF_  64
#define XV_  128
#define YV_  128
#define ZV_  8
#define HW_  (HF_ * WF_)          // 4096

#define ROWF4_  (C_ / 4)          // float4 per pixel: 16
#define LINEF4_ (WF_ * ROWF4_)    // float4 per image row: 1024

// Scratch (allocations forbidden -> __device__ globals)
__device__ float g_mats[BN_ * 12];          // P0,P1,P2 rows per camera
__device__ float g_featsT[BN_ * HW_ * C_];  // feats transposed to (bn, h, w, c)

// ---------------------------------------------------------------------------
// Kernel 1: transpose feats (bn, c, hw) -> (bn, hw, c), float4 both sides.
// Matrix precompute folded into block (0,0,0). PDL trigger at the end.
// ---------------------------------------------------------------------------
__global__ void __launch_bounds__(256) transpose_feats_kernel(
        const float* __restrict__ feats,
        const float* __restrict__ intrins,
        const float* __restrict__ extrins) {
    if (blockIdx.x == 0 && blockIdx.y == 0 && blockIdx.z == 0 && threadIdx.x < BN_) {
        int bn = threadIdx.x;
        const float* E = extrins + bn * 16;
        const float* K = intrins + bn * 16;
        float M[3][4];
#pragma unroll
        for (int i = 0; i < 3; i++) {
            float r0 = E[0 * 4 + i];
            float r1 = E[1 * 4 + i];
            float r2 = E[2 * 4 + i];
            M[i][0] = r0; M[i][1] = r1; M[i][2] = r2;
            M[i][3] = -(r0 * E[3] + r1 * E[7] + r2 * E[11]);
        }
        float fx = K[0] * 0.125f;
        float fy = K[5] * 0.125f;
        float x0 = K[2] * 0.125f;
        float y0 = K[6] * 0.125f;
        float* P = g_mats + bn * 12;
#pragma unroll
        for (int k = 0; k < 4; k++) {
            P[0 * 4 + k] = fx * M[0][k] + x0 * M[2][k];
            P[1 * 4 + k] = fy * M[1][k] + y0 * M[2][k];
            P[2 * 4 + k] = M[2][k];
        }
    }

    __shared__ float tile[32][33];
    int bn = blockIdx.z;
    int c0 = blockIdx.y * 32;
    int p0 = blockIdx.x * 32;
    int tx = threadIdx.x & 7;    // p-float4 index within tile
    int ty = threadIdx.x >> 3;   // c row 0..31

    const float4* in4 = (const float4*)(feats + (size_t)bn * C_ * HW_);
    float4 v = in4[(((c0 + ty) * HW_ + p0) >> 2) + tx];
    tile[ty][4 * tx + 0] = v.x;
    tile[ty][4 * tx + 1] = v.y;
    tile[ty][4 * tx + 2] = v.z;
    tile[ty][4 * tx + 3] = v.w;
    __syncthreads();

    float4 w;
    w.x = tile[4 * tx + 0][ty];
    w.y = tile[4 * tx + 1][ty];
    w.z = tile[4 * tx + 2][ty];
    w.w = tile[4 * tx + 3][ty];
    float4* out4 = (float4*)(g_featsT + (size_t)bn * HW_ * C_);
    out4[(((p0 + ty) * C_ + c0) >> 2) + tx] = w;

#if __CUDA_ARCH__ >= 900
    cudaTriggerProgrammaticLaunchCompletion();
#endif
}

// ---------------------------------------------------------------------------
// Kernel 2: THE R12 CHAMPION main kernel, body byte-identical to the
// 27.68us measurement. Sole addition: cudaGridDependencySynchronize() at
// the very top (PDL) — early-launched blocks wait here, removing the
// inter-kernel launch gap from the wall time without adding any work to
// the kernel body.
// ---------------------------------------------------------------------------
__global__ void __launch_bounds__(128, 9) bev_unproject_kernel(float* __restrict__ out) {
#if __CUDA_ARCH__ >= 900
    cudaGridDependencySynchronize();
#endif

    int t = blockIdx.x * 128 + threadIdx.x;
    int y = t & 127;
    int x = (t >> 7) & 127;
    int z = (t >> 14) & 7;
    int b = t >> 17;

    __shared__ float sm[BN_ * 12];
    if (threadIdx.x < BN_ * 12) sm[threadIdx.x] = g_mats[threadIdx.x];
    __syncthreads();

    // voxel center in cam0/ref coords
    float X = (float)x * 0.8f - 50.8f;
    float Y = (float)y * 0.8f - 50.8f;
    float Z = (float)z * 0.5f - 2.75f;

    const float4* __restrict__ F = (const float4*)g_featsT;
    const float4* p[4];          // per-camera corner00 base pointer
    float ax0[4], ax1[4], ay0[4], ay1[4];
    int mask = 0;

#pragma unroll
    for (int n = 0; n < 4; n++) {
        const float* P = sm + (b * 4 + n) * 12;
        float xp = P[0] * X + P[1] * Y + P[2]  * Z + P[3];
        float yp = P[4] * X + P[5] * Y + P[6]  * Z + P[7];
        float zc = P[8] * X + P[9] * Y + P[10] * Z + P[11];

        float r  = 1.0f / fmaxf(zc, 1e-6f);   // one exact div, two muls
        float sx = xp * r;
        float sy = yp * r;

        bool valid = (sx > -0.5f) & (sx < 63.5f) & (sy > -0.5f) & (sy < 63.5f) & (zc > 0.0f);

        p[n] = F;
        ax0[n] = ax1[n] = ay0[n] = ay1[n] = 0.0f;

        if (valid) {
            float px = sx - 0.5f, py = sy - 0.5f;
            float x0f = floorf(px), y0f = floorf(py);
            float wx = px - x0f,    wy = py - y0f;
            int xi = (int)x0f;      // in [-1, 62]; xi+1 always in-bounds
            int yi = (int)y0f;      // in [-1, 62]; yi+1 always in-bounds
            bool lv = (xi >= 0);
            bool tv = (yi >= 0);
            int xc = lv ? xi : 0;
            int yc = tv ? yi : 0;
            // per-axis weights with edge swap (bit-identical products)
            ax0[n] = lv ? (1.0f - wx) : wx;
            ax1[n] = lv ? wx : 0.0f;
            ay0[n] = tv ? (1.0f - wy) : wy;
            ay1[n] = tv ? wy : 0.0f;
            int bn = b * 4 + n;
            p[n] = F + (size_t)((bn * HF_ + yc) * WF_ + xc) * ROWF4_;
            mask |= (1 << n);
        }
    }

    // fold 1/(eps + #valid) into the y-axis weights
    int cnt = __popc(mask);
    const float r1 = 1.0f / (1e-6f + 1.0f);
    const float r2 = 1.0f / (1e-6f + 2.0f);
    const float r3 = 1.0f / (1e-6f + 3.0f);
    const float r4 = 1.0f / (1e-6f + 4.0f);
    float rcp = (cnt <= 1) ? r1 : (cnt == 2) ? r2 : (cnt == 3) ? r3 : r4;

    float w00[4], w10[4], w01[4], w11[4];
#pragma unroll
    for (int n = 0; n < 4; n++) {
        float sy0 = ay0[n] * rcp, sy1 = ay1[n] * rcp;
        w00[n] = ax0[n] * sy0;
        w10[n] = ax1[n] * sy0;
        w01[n] = ax0[n] * sy1;
        w11[n] = ax1[n] * sy1;
    }

    // out[b, c*8+z, x, y]
    float* ob = out + ((b * C_) * ZV_ + z) * (XV_ * YV_) + x * YV_ + y;
    const int cstride = ZV_ * XV_ * YV_;   // 131072

#pragma unroll
    for (int ch = 0; ch < C_ / 8; ch++) {   // 8 channels = 2 float4 per corner
        float acc[8] = {0.f, 0.f, 0.f, 0.f, 0.f, 0.f, 0.f, 0.f};
#pragma unroll
        for (int n = 0; n < 4; n++) {
            if (mask & (1 << n)) {
                const float4* q = p[n] + ch * 2;
                float a = w00[n], bw = w10[n], c2 = w01[n], d = w11[n];
#pragma unroll
                for (int k = 0; k < 2; k++) {
                    float4 g00 = __ldg(q + k);
                    float4 g10 = __ldg(q + k + ROWF4_);             // +16
                    float4 g01 = __ldg(q + k + LINEF4_);            // +1024
                    float4 g11 = __ldg(q + k + LINEF4_ + ROWF4_);   // +1040
                    acc[4 * k + 0] += ((g00.x * a + g10.x * bw) + g01.x * c2) + g11.x * d;
                    acc[4 * k + 1] += ((g00.y * a + g10.y * bw) + g01.y * c2) + g11.y * d;
                    acc[4 * k + 2] += ((g00.z * a + g10.z * bw) + g01.z * c2) + g11.z * d;
                    acc[4 * k + 3] += ((g00.w * a + g10.w * bw) + g01.w * c2) + g11.w * d;
                }
            }
        }
#pragma unroll
        for (int j = 0; j < 8; j++) {
            ob[(8 * ch + j) * cstride] = acc[j];
        }
    }
}

// ---------------------------------------------------------------------------
extern "C" void kernel_launch(void* const* d_in, const int* in_sizes, int n_in,
                              void* d_out, int out_size) {
    const float* feats   = (const float*)d_in[0];  // (2,4,64,64,64)
    const float* intrins = (const float*)d_in[1];  // (2,4,4,4)
    const float* extrins = (const float*)d_in[2];  // (2,4,4,4)
    float* out = (float*)d_out;                    // (2,512,128,128)

    dim3 tgrid(HW_ / 32, C_ / 32, BN_);
    transpose_feats_kernel<<<tgrid, 256>>>(feats, intrins, extrins);

    // main kernel with Programmatic Dependent Launch: removes the
    // inter-kernel launch gap; the top-of-kernel grid-dependency sync
    // preserves the transpose -> gather ordering.
    cudaLaunchConfig_t cfg = {};
    cfg.gridDim  = dim3((B_ * ZV_ * XV_ * YV_) / 128);   // 2048
    cfg.blockDim = dim3(128);
    cfg.dynamicSmemBytes = 0;
    cfg.stream = 0;
    cudaLaunchAttribute attrs[1];
    attrs[0].id = cudaLaunchAttributeProgrammaticStreamSerialization;
    attrs[0].val.programmaticStreamSerializationAllowed = 1;
    cfg.attrs = attrs;
    cfg.numAttrs = 1;
    cudaLaunchKernelEx(&cfg, bev_unproject_kernel, out);
}